// round 13
// baseline (speedup 1.0000x reference)
#include <cuda_runtime.h>
#include <cuda_bf16.h>
#include <math.h>
#include <stdint.h>

#define N_PTS 8192
#define M_PTS 2048
#define K_LAST 10
#define VARS 3

typedef unsigned long long u64;

// ---------------- packed f32x2 helpers ----------------
__device__ __forceinline__ u64 pk2(float lo, float hi) {
    u64 r; asm("mov.b64 %0,{%1,%2};" : "=l"(r) : "f"(lo), "f"(hi)); return r;
}
__device__ __forceinline__ void unpk2(u64 v, float& lo, float& hi) {
    asm("mov.b64 {%0,%1},%2;" : "=f"(lo), "=f"(hi) : "l"(v));
}
__device__ __forceinline__ u64 f2fma(u64 a, u64 b, u64 c) {
    u64 d; asm("fma.rn.f32x2 %0,%1,%2,%3;" : "=l"(d) : "l"(a), "l"(b), "l"(c)); return d;
}
__device__ __forceinline__ u64 f2mul(u64 a, u64 b) {
    u64 d; asm("mul.rn.f32x2 %0,%1,%2;" : "=l"(d) : "l"(a), "l"(b)); return d;
}
__device__ __forceinline__ u64 dup2(float x) { return pk2(x, x); }

__device__ __forceinline__ float gelu(float x) {
    return 0.5f * x * (1.0f + erff(x * 0.70710678118654752f));
}

// packed GELU (A&S 7.1.26 erf, abs err <= 1.5e-7)
__device__ __forceinline__ u64 gelu2(u64 x) {
    u64 ax = x & 0x7FFFFFFF7FFFFFFFULL;
    u64 z  = f2mul(ax, dup2(0.70710678118654752f));
    u64 den = f2fma(z, dup2(0.3275911f), dup2(1.0f));
    float dl, dh, rl, rh;
    unpk2(den, dl, dh);
    asm("rcp.approx.f32 %0,%1;" : "=f"(rl) : "f"(dl));
    asm("rcp.approx.f32 %0,%1;" : "=f"(rh) : "f"(dh));
    u64 t = pk2(rl, rh);
    u64 z2 = f2mul(z, z);
    u64 m  = f2mul(z2, dup2(-1.4426950408889634f));
    float ml, mh, el, eh;
    unpk2(m, ml, mh);
    asm("ex2.approx.f32 %0,%1;" : "=f"(el) : "f"(ml));
    asm("ex2.approx.f32 %0,%1;" : "=f"(eh) : "f"(mh));
    u64 e = pk2(el, eh);
    u64 p = f2fma(t, dup2(1.061405429f), dup2(-1.453152027f));
    p = f2fma(p, t, dup2(1.421413741f));
    p = f2fma(p, t, dup2(-0.284496736f));
    p = f2fma(p, t, dup2(0.254829592f));
    p = f2mul(p, t);
    u64 np = p ^ 0x8000000080000000ULL;
    u64 u  = f2fma(np, e, dup2(1.0f));
    u64 E  = u | (x & 0x8000000080000000ULL);
    u64 h  = f2fma(E, dup2(0.5f), dup2(0.5f));
    return f2mul(x, h);
}

// pack two floats to bf16x2 (a -> low 16 bits, b -> high)
__device__ __forceinline__ uint32_t pack_bf16(float a, float b) {
    uint32_t r; asm("cvt.rn.bf16x2.f32 %0, %1, %2;" : "=r"(r) : "f"(b), "f"(a));
    return r;
}
// split f32 pair into (hi bf16x2, lo bf16x2)
__device__ __forceinline__ void split_pack(float f0, float f1, uint32_t& hi, uint32_t& lo) {
    hi = pack_bf16(f0, f1);
    float h0 = __uint_as_float(hi << 16);
    float h1 = __uint_as_float(hi & 0xFFFF0000u);
    lo = pack_bf16(f0 - h0, f1 - h1);
}

// m16n8k16 bf16 MMA, D (f32) accumulate in place
__device__ __forceinline__ void mma16816(float* d, const uint32_t* a, uint32_t b0, uint32_t b1) {
    asm volatile(
        "mma.sync.aligned.m16n8k16.row.col.f32.bf16.bf16.f32 "
        "{%0,%1,%2,%3}, {%4,%5,%6,%7}, {%8,%9}, {%0,%1,%2,%3};"
        : "+f"(d[0]), "+f"(d[1]), "+f"(d[2]), "+f"(d[3])
        : "r"(a[0]), "r"(a[1]), "r"(a[2]), "r"(a[3]), "r"(b0), "r"(b1));
}
// 3-term split MMA group (hi*hi + hi*lo + lo*hi)
#define MMA3(d, ah, al, q) do {            \
    mma16816(d, ah, (q).x, (q).y);         \
    mma16816(d, ah, (q).z, (q).w);         \
    mma16816(d, al, (q).x, (q).y);         \
} while (0)

// epilogue: bias + gelu + split for one k-fragment (4 regs) from two d quads
__device__ __forceinline__ void epi_pair(const float* d0, const float* d1,
                                         float bb0, float bb1, float bb2, float bb3,
                                         uint32_t* fh, uint32_t* fl) {
    float q0, q1;
    unpk2(gelu2(pk2(d0[0] + bb0, d0[1] + bb1)), q0, q1); split_pack(q0, q1, fh[0], fl[0]);
    unpk2(gelu2(pk2(d0[2] + bb0, d0[3] + bb1)), q0, q1); split_pack(q0, q1, fh[1], fl[1]);
    unpk2(gelu2(pk2(d1[0] + bb2, d1[1] + bb3)), q0, q1); split_pack(q0, q1, fh[2], fl[2]);
    unpk2(gelu2(pk2(d1[2] + bb2, d1[3] + bb3)), q0, q1); split_pack(q0, q1, fh[3], fl[3]);
}

// ---------------- scratch ----------------
__device__ float g_f0[VARS * N_PTS * 32];
__device__ float g_acc[VARS * N_PTS * 32];
__device__ uint8_t g_blob[2][51200];
// interleaved blob: per set 512B, lane entry = uint4 {bh0, bh1, bl0, bl1}
#define BL1 0        // 30 sets * 512
#define BL2 15360    // 50 sets * 512
#define BL3 40960    // 20 sets * 512
#define BLOB_BYTES 51200

// ---------------- fused weight prep (both phases, all layers) ----------------
__global__ void prep_all_kernel(const float* __restrict__ W10, const float* __restrict__ W11,
                                const float* __restrict__ W12,
                                const float* __restrict__ W20, const float* __restrict__ W21,
                                const float* __restrict__ W22,
                                uint8_t* __restrict__ blob0, uint8_t* __restrict__ blob1) {
    int idx = blockIdx.x * 256 + threadIdx.x;
    if (idx >= 2 * 100 * 32) return;
    int lane = idx & 31;
    int set = (idx >> 5) % 100;
    int phase = (idx >> 5) / 100;
    uint8_t* blob = phase ? blob1 : blob0;

    const float* W; int NT, N, Kreal, sl, ob;
    if (set < 30)      { W = phase ? W20 : W10; NT = 10; N = 80; Kreal = 36; sl = set;      ob = BL1; }
    else if (set < 80) { W = phase ? W21 : W11; NT = 10; N = 80; Kreal = 80; sl = set - 30; ob = BL2; }
    else               { W = phase ? W22 : W12; NT = 4;  N = 32; Kreal = 80; sl = set - 80; ob = BL3; }

    int kt = sl / NT, nt = sl - kt * NT;
    int n = nt * 8 + (lane >> 2);
    int k0 = kt * 16 + 2 * (lane & 3);
    float v[4];
#pragma unroll
    for (int j = 0; j < 4; j++) {
        int k = k0 + (j >> 1) * 8 + (j & 1);
        v[j] = (k < Kreal) ? W[k * N + n] : 0.f;
    }
    uint32_t h0, l0, h1, l1;
    split_pack(v[0], v[1], h0, l0);
    split_pack(v[2], v[3], h1, l1);
    *(uint4*)(blob + ob + (size_t)sl * 512 + lane * 16) = make_uint4(h0, h1, l0, l1);
}

// ---------------- projection MLP ----------------
__global__ void proj_kernel(const float* __restrict__ inp,
                            const float* __restrict__ W0, const float* __restrict__ b0,
                            const float* __restrict__ W1, const float* __restrict__ b1,
                            float* __restrict__ f0) {
    __shared__ float hs[4][64];
    int warp = threadIdx.x >> 5, lane = threadIdx.x & 31;
    int pv = blockIdx.x * 4 + warp;
    if (pv >= VARS * N_PTS) return;
    int v = pv / N_PTS, n = pv - v * N_PTS;
    const float* x = inp + n * (VARS * 8) + v * 8;
    float xr[8];
#pragma unroll
    for (int i = 0; i < 8; i++) xr[i] = x[i];
    float a0 = b0[lane], a1 = b0[lane + 32];
#pragma unroll
    for (int i = 0; i < 8; i++) {
        a0 = fmaf(xr[i], W0[i * 64 + lane], a0);
        a1 = fmaf(xr[i], W0[i * 64 + lane + 32], a1);
    }
    hs[warp][lane]      = gelu(a0);
    hs[warp][lane + 32] = gelu(a1);
    __syncwarp();
    float acc = b1[lane];
#pragma unroll
    for (int h = 0; h < 64; h++) acc = fmaf(hs[warp][h], W1[h * 32 + lane], acc);
    f0[(size_t)pv * 32 + lane] = acc;
}

// ---------------- HMMA edge MLP (paired 2x16-edge tiles per warp) ----------------
// Each warp owns 32 edges; every weight uint4 feeds 6 MMAs (2 tiles x 3 terms).
// Streaming epilogue per k-fragment keeps D transient.
// x row: pos 0..3, f 4..35, zeros 36..47 (stride 52 floats, conflict-free).
#define TPB 128
#define SM_BS0   51200
#define SM_BS1   51520
#define SM_BS2   51840
#define SM_XST   51968          // + warp*6656 (32 rows x 52 floats)
#define SM_SEG   78592          // + warp*128
#define SMEM_BYTES 79104

template <int MODE>
__global__ void __launch_bounds__(TPB, 2)
edge_mma_kernel(const uint8_t* __restrict__ blob,
                const float* __restrict__ b0g, const float* __restrict__ b1g,
                const float* __restrict__ b2g,
                const float* __restrict__ grid_in, const float* __restrict__ grid_out,
                const float* __restrict__ fsrc,
                const int* __restrict__ idxA, const int* __restrict__ idxB,
                float* __restrict__ outbuf, int E) {
    extern __shared__ __align__(16) uint8_t sm[];
    int tid = threadIdx.x;
    int warp = tid >> 5, lane = tid & 31;
    int g = lane >> 2;          // row group 0..7
    int t = lane & 3;           // thread-in-group
    int v = blockIdx.y;

    // stage blob + biases
    {
        const uint4* src = (const uint4*)blob;
        uint4* dst = (uint4*)sm;
        for (int i = tid; i < BLOB_BYTES / 16; i += TPB) dst[i] = src[i];
        float* bs0 = (float*)(sm + SM_BS0);
        float* bs1 = (float*)(sm + SM_BS1);
        float* bs2 = (float*)(sm + SM_BS2);
        if (tid < 80) { bs0[tid] = b0g[tid]; bs1[tid] = b1g[tid]; }
        if (tid < 32) bs2[tid] = b2g[tid];
    }
    __syncthreads();

    float* xst = (float*)(sm + SM_XST + warp * 26624 / 4 * 4);  // 26624B? no: per-warp 6656B
    xst = (float*)(sm + SM_XST + warp * 6656);
    int* seg_sh = (int*)(sm + SM_SEG + warp * 128);
    const float* bs0 = (const float*)(sm + SM_BS0);
    const float* bs1 = (const float*)(sm + SM_BS1);
    const float* bs2 = (const float*)(sm + SM_BS2);

    // ---- gather: 1 lane per edge (32 edges/warp) ----
    {
        int e = blockIdx.x * 128 + warp * 32 + lane;
        bool gv = e < E;
        int ee = gv ? e : 0;
        int jn = idxA[ee];
        int sg = (MODE == 0) ? idxB[ee] : ee / K_LAST;
        seg_sh[lane] = gv ? sg : -1;
        float4 pos = make_float4(0.f, 0.f, 0.f, 0.f);
        if (gv) {
            pos.x = grid_in[2 * jn]; pos.y = grid_in[2 * jn + 1];
            if (MODE == 0) { pos.z = grid_in[2 * sg];  pos.w = grid_in[2 * sg + 1]; }
            else           { pos.z = grid_out[2 * sg]; pos.w = grid_out[2 * sg + 1]; }
        }
        float4* xrow = (float4*)(xst + lane * 52);
        xrow[0] = pos;
        const float4* fp = (const float4*)(fsrc + ((size_t)v * N_PTS + jn) * 32);
#pragma unroll
        for (int q = 0; q < 8; q++) xrow[1 + q] = fp[q];
        float4 z = make_float4(0.f, 0.f, 0.f, 0.f);
        xrow[9] = z; xrow[10] = z; xrow[11] = z;
    }
    __syncwarp();

    // ---- A1 fragments (both tiles, 3 k-tiles) ----
    uint32_t a1h[2][3][4], a1l[2][3][4];
#pragma unroll
    for (int T = 0; T < 2; T++)
#pragma unroll
        for (int kt = 0; kt < 3; kt++)
#pragma unroll
            for (int rr = 0; rr < 4; rr++) {
                int row = T * 16 + g + (rr & 1) * 8;
                int col = 16 * kt + 2 * t + (rr >> 1) * 8;
                u64 pv_ = *(const u64*)(xst + row * 52 + col);
                float f0, f1; unpk2(pv_, f0, f1);
                split_pack(f0, f1, a1h[T][kt][rr], a1l[T][kt][rr]);
            }

    // ---- layer 1: K=48, N=80; streaming epilogue -> A2 fragments ----
    uint32_t a2h[2][5][4], a2l[2][5][4];
#pragma unroll
    for (int kt2 = 0; kt2 < 5; kt2++) {
        float d[2][2][4];
#pragma unroll
        for (int h = 0; h < 2; h++) {
            int nt = 2 * kt2 + h;
#pragma unroll
            for (int T = 0; T < 2; T++) {
                d[h][T][0] = 0.f; d[h][T][1] = 0.f; d[h][T][2] = 0.f; d[h][T][3] = 0.f;
            }
#pragma unroll
            for (int kt = 0; kt < 3; kt++) {
                uint4 q = *(const uint4*)(sm + BL1 + (size_t)(kt * 10 + nt) * 512 + lane * 16);
                MMA3(d[h][0], a1h[0][kt], a1l[0][kt], q);
                MMA3(d[h][1], a1h[1][kt], a1l[1][kt], q);
            }
        }
        float bb0, bb1, bb2, bb3;
        unpk2(*(const u64*)(bs0 + 16 * kt2 + 2 * t), bb0, bb1);
        unpk2(*(const u64*)(bs0 + 16 * kt2 + 8 + 2 * t), bb2, bb3);
#pragma unroll
        for (int T = 0; T < 2; T++)
            epi_pair(d[0][T], d[1][T], bb0, bb1, bb2, bb3, a2h[T][kt2], a2l[T][kt2]);
    }

    // ---- layer 2: K=80, N=80; streaming epilogue -> A3 fragments ----
    uint32_t a3h[2][5][4], a3l[2][5][4];
#pragma unroll
    for (int kt2 = 0; kt2 < 5; kt2++) {
        float d[2][2][4];
#pragma unroll
        for (int h = 0; h < 2; h++) {
            int nt = 2 * kt2 + h;
#pragma unroll
            for (int T = 0; T < 2; T++) {
                d[h][T][0] = 0.f; d[h][T][1] = 0.f; d[h][T][2] = 0.f; d[h][T][3] = 0.f;
            }
#pragma unroll
            for (int kt = 0; kt < 5; kt++) {
                uint4 q = *(const uint4*)(sm + BL2 + (size_t)(kt * 10 + nt) * 512 + lane * 16);
                MMA3(d[h][0], a2h[0][kt], a2l[0][kt], q);
                MMA3(d[h][1], a2h[1][kt], a2l[1][kt], q);
            }
        }
        float bb0, bb1, bb2, bb3;
        unpk2(*(const u64*)(bs1 + 16 * kt2 + 2 * t), bb0, bb1);
        unpk2(*(const u64*)(bs1 + 16 * kt2 + 8 + 2 * t), bb2, bb3);
#pragma unroll
        for (int T = 0; T < 2; T++)
            epi_pair(d[0][T], d[1][T], bb0, bb1, bb2, bb3, a3h[T][kt2], a3l[T][kt2]);
    }

    // ---- layer 3: K=80, N=32; scatter per n-tile ----
    float scale = (MODE == 0) ? 1.0f : 0.1f;
#pragma unroll
    for (int nt = 0; nt < 4; nt++) {
        float d[2][4];
#pragma unroll
        for (int T = 0; T < 2; T++) {
            d[T][0] = 0.f; d[T][1] = 0.f; d[T][2] = 0.f; d[T][3] = 0.f;
        }
#pragma unroll
        for (int kt = 0; kt < 5; kt++) {
            uint4 q = *(const uint4*)(sm + BL3 + (size_t)(kt * 4 + nt) * 512 + lane * 16);
            MMA3(d[0], a3h[0][kt], a3l[0][kt], q);
            MMA3(d[1], a3h[1][kt], a3l[1][kt], q);
        }
        float bb0, bb1;
        unpk2(*(const u64*)(bs2 + 8 * nt + 2 * t), bb0, bb1);
        int c0 = 8 * nt + 2 * t;
#pragma unroll
        for (int T = 0; T < 2; T++) {
            int sgA = seg_sh[T * 16 + g];
            int sgB = seg_sh[T * 16 + g + 8];
            float* dstA = nullptr; float* dstB = nullptr;
            if (MODE == 0) {
                if (sgA >= 0) dstA = outbuf + ((size_t)v * N_PTS + sgA) * 32;
                if (sgB >= 0) dstB = outbuf + ((size_t)v * N_PTS + sgB) * 32;
            } else {
                if (sgA >= 0) dstA = outbuf + (size_t)sgA * (VARS * 32) + v * 32;
                if (sgB >= 0) dstB = outbuf + (size_t)sgB * (VARS * 32) + v * 32;
            }
            if (dstA) {
                atomicAdd(dstA + c0,     (d[T][0] + bb0) * scale);
                atomicAdd(dstA + c0 + 1, (d[T][1] + bb1) * scale);
            }
            if (dstB) {
                atomicAdd(dstB + c0,     (d[T][2] + bb0) * scale);
                atomicAdd(dstB + c0 + 1, (d[T][3] + bb1) * scale);
            }
        }
    }
}

// f1 = segment_sum * inv_count + f0 (in place)
__global__ void f1_kernel(float* __restrict__ f0, const float* __restrict__ acc,
                          const int* __restrict__ counts) {
    int idx = blockIdx.x * 256 + threadIdx.x;
    if (idx >= VARS * N_PTS * 32) return;
    int n = (idx >> 5) % N_PTS;
    int c = counts[n];
    float inv = 1.0f / (float)(c > 1 ? c : 1);
    f0[idx] = fmaf(acc[idx], inv, f0[idx]);
}

extern "C" void kernel_launch(void* const* d_in, const int* in_sizes, int n_in,
                              void* d_out, int out_size) {
    const float* inp   = (const float*)d_in[0];
    const float* gin   = (const float*)d_in[1];
    const float* gout  = (const float*)d_in[2];
    const float* pW0   = (const float*)d_in[3];
    const float* pb0   = (const float*)d_in[4];
    const float* pW1   = (const float*)d_in[5];
    const float* pb1   = (const float*)d_in[6];
    const float* i0W0  = (const float*)d_in[7];
    const float* i0b0  = (const float*)d_in[8];
    const float* i0W1  = (const float*)d_in[9];
    const float* i0b1  = (const float*)d_in[10];
    const float* i0W2  = (const float*)d_in[11];
    const float* i0b2  = (const float*)d_in[12];
    const float* i1W0  = (const float*)d_in[13];
    const float* i1b0  = (const float*)d_in[14];
    const float* i1W1  = (const float*)d_in[15];
    const float* i1b1  = (const float*)d_in[16];
    const float* i1W2  = (const float*)d_in[17];
    const float* i1b2  = (const float*)d_in[18];
    const int* nbr_index  = (const int*)d_in[19];
    const int* nbr_seg    = (const int*)d_in[20];
    const int* nbr_counts = (const int*)d_in[21];
    const int* nbr_last   = (const int*)d_in[22];
    int E = in_sizes[19];

    float *f0, *acc;
    uint8_t* blob;
    cudaGetSymbolAddress((void**)&f0,   g_f0);
    cudaGetSymbolAddress((void**)&acc,  g_acc);
    cudaGetSymbolAddress((void**)&blob, g_blob);
    uint8_t* blob0 = blob;
    uint8_t* blob1 = blob + BLOB_BYTES;

    cudaMemsetAsync(acc, 0, sizeof(float) * VARS * N_PTS * 32);
    cudaMemsetAsync(d_out, 0, sizeof(float) * (size_t)out_size);

    prep_all_kernel<<<(2 * 100 * 32 + 255) / 256, 256>>>(i0W0, i0W1, i0W2,
                                                         i1W0, i1W1, i1W2, blob0, blob1);

    proj_kernel<<<(VARS * N_PTS + 3) / 4, 128>>>(inp, pW0, pb0, pW1, pb1, f0);

    cudaFuncSetAttribute(edge_mma_kernel<0>, cudaFuncAttributeMaxDynamicSharedMemorySize, SMEM_BYTES);
    cudaFuncSetAttribute(edge_mma_kernel<1>, cudaFuncAttributeMaxDynamicSharedMemorySize, SMEM_BYTES);

    dim3 g1((unsigned)((E + 127) / 128), VARS);
    edge_mma_kernel<0><<<g1, TPB, SMEM_BYTES>>>(blob0, i0b0, i0b1, i0b2,
                                                gin, nullptr, f0, nbr_index, nbr_seg, acc, E);

    f1_kernel<<<(VARS * N_PTS * 32 + 255) / 256, 256>>>(f0, acc, nbr_counts);

    int E2 = M_PTS * K_LAST;
    dim3 g2((unsigned)((E2 + 127) / 128), VARS);
    edge_mma_kernel<1><<<g2, TPB, SMEM_BYTES>>>(blob1, i1b0, i1b1, i1b2,
                                                gin, gout, f0, nbr_last, nullptr, (float*)d_out, E2);
}